// round 16
// baseline (speedup 1.0000x reference)
#include <cuda_runtime.h>
#include <cuda_bf16.h>
#include <cuda_fp16.h>

// Problem constants (shapes fixed by the dataset)
#define NN   8192
#define EE   65536
#define INC  64
#define OUTC 16
#define EF   8
#define L1   48
#define L2   32

#define C1TOT 480   // Y1 (EF*L1=384) + Z1 (48) + R1 (48), K=64
#define C2TOT 320   // Y2 (EF*L2=256) + Z2 (32) + R2 (32), K=48

#define NPB 16  // nodes per block (node2 register tile height)

// ---------------- scratch (device globals; no allocation allowed) ----------
__device__ __half dXh[(size_t)NN * 64];        // fp16 copy of x
__device__ __half dY1h[(size_t)NN * EF * L1];  // fp16 gather payload  6.3 MB
__device__ __half dZ1h[NN * L1];               // fp16 gather payload
__device__ float  dAgg1[NN * L1];
__device__ __half dY2h[(size_t)NN * EF * L2];  // fp16 gather payload  4.2 MB
__device__ __half dZ2h[NN * L2];               // fp16 gather payload
__device__ float  dAgg2[NN * L2];
__device__ float  dDeg[NN];
__device__ float  dRs[NN];                     // rsqrt(deg)
__device__ float  dG[NN * 2 * OUTC];           // [n][c], c<16 mu, c>=16 ls
__device__ __half dW1ct[C1TOT * 64];           // fp16, c-major: [c][k]
__device__ float  dW2km[48 * C2TOT];           // k-major: [k][c]
__device__ float  dWgKM[32 * 32];              // k-major: [k][c]

__device__ __forceinline__ void red_add_v4(float* addr, float4 v) {
    asm volatile("red.global.add.v4.f32 [%0], {%1, %2, %3, %4};"
                 :: "l"(addr), "f"(v.x), "f"(v.y), "f"(v.z), "f"(v.w) : "memory");
}

// ---------------- kernel 0: weight pre-transpose ----------------------------
__global__ void prep_weights(const float* __restrict__ nn1_w, const float* __restrict__ nn1_b,
                             const float* __restrict__ root1,
                             const float* __restrict__ nn2_w, const float* __restrict__ nn2_b,
                             const float* __restrict__ root2,
                             const float* __restrict__ mu_w,  const float* __restrict__ ls_w) {
    int idx = blockIdx.x * blockDim.x + threadIdx.x;
    if (idx < C1TOT * 64) {
        int k = idx / C1TOT, c = idx - k * C1TOT;
        float v;
        if (c < EF * L1)            { int f = c / L1, j = c % L1; v = nn1_w[f * (INC * L1) + k * L1 + j]; }
        else if (c < EF * L1 + L1)  { int j = c - EF * L1;        v = nn1_b[k * L1 + j]; }
        else                        { int j = c - EF * L1 - L1;   v = root1[k * L1 + j]; }
        dW1ct[c * 64 + k] = __float2half(v);   // fp16, c-major for mma B fragments
    }
    int i2 = idx - C1TOT * 64;
    if (i2 >= 0 && i2 < C2TOT * 48) {
        int k = i2 / C2TOT, c = i2 - k * C2TOT;
        float v;
        if (c < EF * L2)            { int f = c / L2, j = c % L2; v = nn2_w[f * (L1 * L2) + k * L2 + j]; }
        else if (c < EF * L2 + L2)  { int j = c - EF * L2;        v = nn2_b[k * L2 + j]; }
        else                        { int j = c - EF * L2 - L2;   v = root2[k * L2 + j]; }
        dW2km[i2] = v;
    }
    int i3 = i2 - C2TOT * 48;
    if (i3 >= 0 && i3 < 32 * 32) {
        int k = i3 >> 5, c = i3 & 31;   // k-major output: [k][c]
        dWgKM[i3] = (c < OUTC) ? mu_w[k * OUTC + c] : ls_w[k * OUTC + (c - OUTC)];
    }
}

// ---------------- kernel: x -> fp16 + deg init ------------------------------
__global__ void xcvt_kernel(const float* __restrict__ x) {
    int i = blockIdx.x * blockDim.x + threadIdx.x;   // over NN*64/4
    float4 v = ((const float4*)x)[i];
    *(__half2*)(dXh + (size_t)i * 4)     = __floats2half2_rn(v.x, v.y);
    *(__half2*)(dXh + (size_t)i * 4 + 2) = __floats2half2_rn(v.z, v.w);
    if (i < NN) dDeg[i] = 1.0f;
}

// ---------------- kernel: node transform layer 1 (HMMA) ---------------------
// C[8192x480] = Xh[8192x64] @ W1[64x480], fp16 in / fp32 accum.
// 128 blocks x 256 thr. Warp w: rows n0+16*(w>>1), cols 240*(w&1)+[0,240).
__global__ __launch_bounds__(256) void node1_mma(const float* __restrict__ bias1) {
    int tid = threadIdx.x, w = tid >> 5, l = tid & 31;
    int n0 = blockIdx.x * 64;
    int row_lo = n0 + (w >> 1) * 16 + (l >> 2);
    int chalf = w & 1;
    int kq = (l & 3) * 2;

    unsigned a[4][4];
#pragma unroll
    for (int kk = 0; kk < 4; kk++) {
        int k0 = kk * 16 + kq;
        a[kk][0] = *(const unsigned*)(dXh + (size_t)row_lo * 64 + k0);
        a[kk][1] = *(const unsigned*)(dXh + (size_t)(row_lo + 8) * 64 + k0);
        a[kk][2] = *(const unsigned*)(dXh + (size_t)row_lo * 64 + k0 + 8);
        a[kk][3] = *(const unsigned*)(dXh + (size_t)(row_lo + 8) * 64 + k0 + 8);
    }

    for (int t = 0; t < 30; t++) {
        int cbase = chalf * 240 + t * 8;
        int ng = cbase + (l >> 2);
        float c0 = 0.f, c1 = 0.f, c2 = 0.f, c3 = 0.f;
#pragma unroll
        for (int kk = 0; kk < 4; kk++) {
            int k0 = kk * 16 + kq;
            unsigned b0 = *(const unsigned*)(dW1ct + ng * 64 + k0);
            unsigned b1 = *(const unsigned*)(dW1ct + ng * 64 + k0 + 8);
            asm("mma.sync.aligned.m16n8k16.row.col.f32.f16.f16.f32 "
                "{%0,%1,%2,%3}, {%4,%5,%6,%7}, {%8,%9}, {%0,%1,%2,%3};"
                : "+f"(c0), "+f"(c1), "+f"(c2), "+f"(c3)
                : "r"(a[kk][0]), "r"(a[kk][1]), "r"(a[kk][2]), "r"(a[kk][3]),
                  "r"(b0), "r"(b1));
        }
        int col = cbase + kq;
        int rlo = row_lo, rhi = row_lo + 8;
        if (cbase < EF * L1) {
            *(__half2*)(dY1h + (size_t)rlo * (EF * L1) + col) = __floats2half2_rn(c0, c1);
            *(__half2*)(dY1h + (size_t)rhi * (EF * L1) + col) = __floats2half2_rn(c2, c3);
        } else if (cbase < EF * L1 + L1) {
            int j = col - EF * L1;
            *(__half2*)(dZ1h + rlo * L1 + j) = __floats2half2_rn(c0, c1);
            *(__half2*)(dZ1h + rhi * L1 + j) = __floats2half2_rn(c2, c3);
        } else {
            int j = col - EF * L1 - L1;
            float2 b = *(const float2*)(bias1 + j);
            *(float2*)(dAgg1 + rlo * L1 + j) = make_float2(c0 + b.x, c1 + b.y);
            *(float2*)(dAgg1 + rhi * L1 + j) = make_float2(c2 + b.x, c3 + b.y);
        }
    }
}

// ---------------- kernel: edge scatter layer 1 (fp16 gather, vec4 red) ------
__global__ void edge1_kernel(const int* __restrict__ ei, const float* __restrict__ ea) {
    int idx = blockIdx.x * blockDim.x + threadIdx.x;
    if (idx >= EE * 12) return;
    int e = idx / 12;
    int q = idx - e * 12;
    int j = q * 4;
    int s = ei[e];
    int d = ei[EE + e];
    float4 ea0 = ((const float4*)(ea + e * EF))[0];
    float4 ea1 = ((const float4*)(ea + e * EF))[1];
    const __half* y = dY1h + (size_t)s * (EF * L1) + j;
    uint2 zr = *(const uint2*)(dZ1h + s * L1 + j);
    float2 z0 = __half22float2(*reinterpret_cast<const __half2*>(&zr.x));
    float2 z1 = __half22float2(*reinterpret_cast<const __half2*>(&zr.y));
    float4 m = make_float4(z0.x, z0.y, z1.x, z1.y);
#define E1STEP(F, A) { \
    uint2 r = *(const uint2*)(y + (F) * L1); \
    float2 f0 = __half22float2(*reinterpret_cast<const __half2*>(&r.x)); \
    float2 f1 = __half22float2(*reinterpret_cast<const __half2*>(&r.y)); \
    m.x += (A) * f0.x; m.y += (A) * f0.y; m.z += (A) * f1.x; m.w += (A) * f1.y; }
    E1STEP(0, ea0.x) E1STEP(1, ea0.y) E1STEP(2, ea0.z) E1STEP(3, ea0.w)
    E1STEP(4, ea1.x) E1STEP(5, ea1.y) E1STEP(6, ea1.z) E1STEP(7, ea1.w)
#undef E1STEP
    if (q == 0) atomicAdd(&dDeg[d], 1.0f);
    red_add_v4(&dAgg1[d * L1 + j], m);
}

// ---------------- kernel: node transform layer 2 (scalar) -------------------
__global__ __launch_bounds__(C2TOT) void node2_kernel(const float* __restrict__ bias2) {
    __shared__ float hs[NPB * 48];
    int n0 = blockIdx.x * NPB;
    int c = threadIdx.x;
    if (c < NPB * 48 / 4) {
        float4 v = ((const float4*)(dAgg1 + n0 * L1))[c];
        v.x = fmaxf(v.x, 0.f); v.y = fmaxf(v.y, 0.f);
        v.z = fmaxf(v.z, 0.f); v.w = fmaxf(v.w, 0.f);
        ((float4*)hs)[c] = v;
    }
    if (c < NPB) dRs[n0 + c] = rsqrtf(dDeg[n0 + c]);  // deg final after edge1
    __syncthreads();

    float acc[NPB];
#pragma unroll
    for (int n = 0; n < NPB; n++) acc[n] = 0.0f;
    const float* wp = dW2km + c;
#pragma unroll 8
    for (int k4 = 0; k4 < 12; k4++) {
        float w0 = wp[(4 * k4 + 0) * C2TOT];
        float w1 = wp[(4 * k4 + 1) * C2TOT];
        float w2 = wp[(4 * k4 + 2) * C2TOT];
        float w3 = wp[(4 * k4 + 3) * C2TOT];
#pragma unroll
        for (int n = 0; n < NPB; n++) {
            float4 xv = ((const float4*)(hs + n * 48))[k4];  // broadcast LDS
            acc[n] += xv.x * w0 + xv.y * w1 + xv.z * w2 + xv.w * w3;
        }
    }
    if (c < EF * L2) {
#pragma unroll
        for (int n = 0; n < NPB; n++)
            dY2h[(size_t)(n0 + n) * (EF * L2) + c] = __float2half(acc[n]);
    } else if (c < EF * L2 + L2) {
        int j = c - EF * L2;
#pragma unroll
        for (int n = 0; n < NPB; n++) dZ2h[(n0 + n) * L2 + j] = __float2half(acc[n]);
    } else {
        int j = c - EF * L2 - L2;
        float b = bias2[j];
#pragma unroll
        for (int n = 0; n < NPB; n++) dAgg2[(n0 + n) * L2 + j] = acc[n] + b;
    }
}

// ---------------- kernel: edge scatter layer 2 (fp16 gather, vec4 red) ------
__global__ void edge2_kernel(const int* __restrict__ ei, const float* __restrict__ ea) {
    int idx = blockIdx.x * blockDim.x + threadIdx.x;
    if (idx >= EE * 8) return;
    int e = idx >> 3;
    int q = idx & 7;
    int j = q * 4;
    int s = ei[e];
    int d = ei[EE + e];
    float4 ea0 = ((const float4*)(ea + e * EF))[0];
    float4 ea1 = ((const float4*)(ea + e * EF))[1];
    const __half* y = dY2h + (size_t)s * (EF * L2) + j;
    uint2 zr = *(const uint2*)(dZ2h + s * L2 + j);
    float2 z0 = __half22float2(*reinterpret_cast<const __half2*>(&zr.x));
    float2 z1 = __half22float2(*reinterpret_cast<const __half2*>(&zr.y));
    float4 m = make_float4(z0.x, z0.y, z1.x, z1.y);
#define E2STEP(F, A) { \
    uint2 r = *(const uint2*)(y + (F) * L2); \
    float2 f0 = __half22float2(*reinterpret_cast<const __half2*>(&r.x)); \
    float2 f1 = __half22float2(*reinterpret_cast<const __half2*>(&r.y)); \
    m.x += (A) * f0.x; m.y += (A) * f0.y; m.z += (A) * f1.x; m.w += (A) * f1.y; }
    E2STEP(0, ea0.x) E2STEP(1, ea0.y) E2STEP(2, ea0.z) E2STEP(3, ea0.w)
    E2STEP(4, ea1.x) E2STEP(5, ea1.y) E2STEP(6, ea1.z) E2STEP(7, ea1.w)
#undef E2STEP
    red_add_v4(&dAgg2[d * L2 + j], m);
}

// ---------------- kernel: h2 relu + head GEMV + out self-term ---------------
__global__ void node3_kernel(const float* __restrict__ mu_b, const float* __restrict__ ls_b,
                             float* __restrict__ out) {
    int idx = blockIdx.x * blockDim.x + threadIdx.x;
    if (idx >= NN * 32) return;
    int n = idx >> 5;
    int c = idx & 31;
    const float* a = dAgg2 + n * L2;
    float acc = 0.0f;
#pragma unroll
    for (int k = 0; k < 32; k++) acc += fmaxf(a[k], 0.0f) * dWgKM[k * 32 + c];
    dG[idx] = acc;
    float rs = dRs[n];
    float inv = rs * rs;  // 1/deg
    if (c < OUTC) out[n * OUTC + c] = acc * inv + mu_b[c];
    else          out[(size_t)NN * OUTC + n * OUTC + (c - OUTC)] = acc * inv + ls_b[c - OUTC];
}

// ---------------- kernel: GCN edge aggregation (vec4 red) -------------------
__global__ void edge3_kernel(const int* __restrict__ ei, float* __restrict__ out) {
    int idx = blockIdx.x * blockDim.x + threadIdx.x;
    if (idx >= EE * 8) return;
    int e = idx >> 3;
    int q = idx & 7;
    int c = q * 4;
    int s = ei[e];
    int d = ei[EE + e];
    float norm = dRs[s] * dRs[d];
    float4 g = *(const float4*)(dG + s * 32 + c);
    g.x *= norm; g.y *= norm; g.z *= norm; g.w *= norm;
    float* dst = (c < OUTC) ? &out[d * OUTC + c]
                            : &out[(size_t)NN * OUTC + d * OUTC + (c - OUTC)];
    red_add_v4(dst, g);
}

// ---------------- launch ----------------------------------------------------
extern "C" void kernel_launch(void* const* d_in, const int* in_sizes, int n_in,
                              void* d_out, int out_size) {
    const float* x     = (const float*)d_in[0];
    const int*   ei    = (const int*)  d_in[1];
    const float* ea    = (const float*)d_in[2];
    const float* nn1_w = (const float*)d_in[3];
    const float* nn1_b = (const float*)d_in[4];
    const float* root1 = (const float*)d_in[5];
    const float* bias1 = (const float*)d_in[6];
    const float* nn2_w = (const float*)d_in[7];
    const float* nn2_b = (const float*)d_in[8];
    const float* root2 = (const float*)d_in[9];
    const float* bias2 = (const float*)d_in[10];
    const float* mu_w  = (const float*)d_in[11];
    const float* mu_b  = (const float*)d_in[12];
    const float* ls_w  = (const float*)d_in[13];
    const float* ls_b  = (const float*)d_in[14];
    float* out = (float*)d_out;

    int prep_threads = C1TOT * 64 + C2TOT * 48 + 32 * 32;
    prep_weights<<<(prep_threads + 255) / 256, 256>>>(nn1_w, nn1_b, root1,
                                                      nn2_w, nn2_b, root2, mu_w, ls_w);
    xcvt_kernel<<<NN * 64 / 4 / 256, 256>>>(x);
    node1_mma<<<NN / 64, 256>>>(bias1);
    edge1_kernel<<<(EE * 12 + 255) / 256, 256>>>(ei, ea);
    node2_kernel<<<NN / NPB, C2TOT>>>(bias2);
    edge2_kernel<<<(EE * 8 + 255) / 256, 256>>>(ei, ea);
    node3_kernel<<<(NN * 32 + 255) / 256, 256>>>(mu_b, ls_b, out);
    edge3_kernel<<<(EE * 8 + 255) / 256, 256>>>(ei, out);
}